// round 17
// baseline (speedup 1.0000x reference)
#include <cuda_runtime.h>
#include <cuda_fp16.h>
#include <cstdint>
#include <math.h>

#define EPS 1e-5f

constexpr int Bn = 256, CT = 256, CR = 192, CG = 64;
constexpr int H = 19, W = 19, HW = 361;
constexpr int PP = 504;   // padded 21x24 pixel plane

constexpr int NCB1 = 4, NKC1 = 9 * NCB1;   // 36 chunks (tap-major)
constexpr int NCB2 = 3, NKC2 = 9 * NCB2;   // 27 chunks

constexpr int NTILE = 192;                        // pixels per CTA
constexpr int ASTH = 72, ABUFH = 128 * ASTH;      // 9216 halves
constexpr int BSTH = 72, BBUFH = NTILE * BSTH;    // 13824 halves
constexpr int BUFH = ABUFH + BBUFH;               // 23040 halves/stage
constexpr int SMEMSZ = 2 * BUFH * 2;              // 92160 B dynamic

// ---- device scratch ----
__device__ float  g_reg [Bn * CR * HW];
__device__ float  g_gp  [Bn * CG * HW];
__device__ float  g_gpo [Bn * CR];
__device__ __half g_wA1 [2 * NKC1 * 8192];        // [mt][kc][row128][k64]
__device__ __half g_wA2 [2 * NKC2 * 8192];
__device__ __half g_h1 [(size_t)Bn * PP * CT];    // NHWC padded act for conv1
__device__ __half g_h2 [(size_t)Bn * PP * CR];    // NHWC padded act for conv2

__device__ __forceinline__ float mishf(float x) {
    if (x > 20.f) return x;
    float t = __expf(x);
    float u = fmaf(t, t, 2.f * t);
    return x * __fdividef(u, u + 2.f);
}
__device__ __forceinline__ void mma_f16(float* d, const uint32_t* a, const uint32_t* b) {
    asm volatile(
        "mma.sync.aligned.m16n8k16.row.col.f32.f16.f16.f32 "
        "{%0,%1,%2,%3}, {%4,%5,%6,%7}, {%8,%9}, {%0,%1,%2,%3};"
        : "+f"(d[0]), "+f"(d[1]), "+f"(d[2]), "+f"(d[3])
        : "r"(a[0]), "r"(a[1]), "r"(a[2]), "r"(a[3]), "r"(b[0]), "r"(b[1]));
}
__device__ __forceinline__ uint32_t smem_u32(const void* p) {
    uint32_t a;
    asm("{ .reg .u64 t; cvta.to.shared.u64 t, %1; cvt.u32.u64 %0, t; }" : "=r"(a) : "l"(p));
    return a;
}
__device__ __forceinline__ void ldmx4(uint32_t* r, uint32_t addr) {
    asm volatile("ldmatrix.sync.aligned.m8n8.x4.shared.b16 {%0,%1,%2,%3}, [%4];"
                 : "=r"(r[0]), "=r"(r[1]), "=r"(r[2]), "=r"(r[3]) : "r"(addr));
}
__device__ __forceinline__ void cpa16(uint32_t dst, const void* src) {
    asm volatile("cp.async.cg.shared.global [%0], [%1], 16;" :: "r"(dst), "l"(src));
}
#define CP_COMMIT() asm volatile("cp.async.commit_group;" ::: "memory")
#define CP_WAIT0()  asm volatile("cp.async.wait_group 0;" ::: "memory")

// ---- zero only BORDER pixels of the NHWC buffers ----
// Grid: (Bn * PP) blocks of 64 threads; border blocks write channel rows of zero.
__global__ void k_zero() {
    int bp = blockIdx.x;
    int img = bp / PP, p = bp - img * PP;
    int y = p / 24, xc = p - y * 24;
    if (y >= 1 && y <= H && xc >= 1 && xc <= W) return;   // interior: overwritten by k_act
    int t = threadIdx.x;
    uint4 z = make_uint4(0, 0, 0, 0);
    if (t < 32) ((uint4*)(g_h1 + ((size_t)img * PP + p) * CT))[t] = z;
    if (t < 24) ((uint4*)(g_h2 + ((size_t)img * PP + p) * CR))[t] = z;
}

// ---- weight prep: OIHW -> [mt][kc=(r,cb)][row][k64] fp16 ----
__global__ void k_wA1(const float* __restrict__ w1a, const float* __restrict__ w1b) {
    int i = blockIdx.x * blockDim.x + threadIdx.x;
    if (i >= 2 * NKC1 * 8192) return;
    int blk = i >> 13, q = i & 8191;
    int mt = blk / NKC1, kc = blk % NKC1;
    int row = q >> 6, k = q & 63;
    int r = kc >> 2, cb = kc & 3;
    int ci = cb * 64 + k;
    int cout = mt * 128 + row;
    float v = (cout < CR) ? w1a[(cout * CT + ci) * 9 + r]
                          : w1b[((cout - CR) * CT + ci) * 9 + r];
    g_wA1[i] = __float2half_rn(v);
}
__global__ void k_wA2(const float* __restrict__ w2) {
    int i = blockIdx.x * blockDim.x + threadIdx.x;
    if (i >= 2 * NKC2 * 8192) return;
    int blk = i >> 13, q = i & 8191;
    int mt = blk / NKC2, kc = blk % NKC2;
    int row = q >> 6, k = q & 63;
    int r = kc / 3, cb = kc - r * 3;
    int ci = cb * 64 + k;
    int cout = mt * 128 + row;
    g_wA2[i] = __float2half_rn(w2[(cout * CR + ci) * 9 + r]);
}

// ---- BN+mish + NCHW->NHWC fp16 transpose (interior pixels only) ----
template <int CIN, int MODE>
__global__ __launch_bounds__(256)
void k_act(const float* __restrict__ xarg,
           const float* __restrict__ bg, const float* __restrict__ bb,
           const float* __restrict__ bm, const float* __restrict__ bv) {
    __shared__ __half sm[361 * 66];
    __shared__ float ssc[64], sbs[64];
    const int cb = blockIdx.x, img = blockIdx.y;
    const int tid = threadIdx.x;

    const float* src = (MODE == 0) ? xarg : (const float*)g_reg;
    __half* dst = (MODE == 0) ? g_h1 : g_h2;

    if (tid < 64) {
        int c = cb * 64 + tid;
        float sc = bg[c] * rsqrtf(bv[c] + EPS);
        float bs = fmaf(-bm[c], sc, bb[c]);
        if (MODE == 1) bs = fmaf(g_gpo[img * CR + c], sc, bs);
        ssc[tid] = sc; sbs[tid] = bs;
    }
    __syncthreads();

    const float* inb = src + ((size_t)img * CIN + cb * 64) * HW;
    for (int i = tid; i < 64 * HW; i += 256) {
        int ci = i / HW, p = i - ci * HW;
        sm[p * 66 + ci] = __float2half_rn(mishf(fmaf(inb[i], ssc[ci], sbs[ci])));
    }
    __syncthreads();

    __half* db = dst + (size_t)img * PP * CIN + cb * 64;
    for (int i = tid; i < HW * 32; i += 256) {
        int p = i >> 5, t = i & 31;
        int ctr = (p / 19 + 1) * 24 + (p % 19) + 1;
        uint32_t lo = __half_as_ushort(sm[p * 66 + 2 * t]);
        uint32_t hi = __half_as_ushort(sm[p * 66 + 2 * t + 1]);
        *(uint32_t*)(db + (size_t)ctr * CIN + 2 * t) = lo | (hi << 16);
    }
}

// ---- fp16 implicit-GEMM conv: CTA 128x192, tap-shifted NHWC B, K64 chunks ----
// Single-barrier pipeline: WAIT0 -> bar -> stage(kc+1) -> MMA(kc).
template <int CIN, int NCB, int MODE>
__global__ __launch_bounds__(256, 2)
void k_convtc(const float* __restrict__ bg, const float* __restrict__ bb,
              const float* __restrict__ bm, const float* __restrict__ bv,
              const float* __restrict__ resid, float* __restrict__ outp) {
    extern __shared__ __half smh[];
    constexpr int NKC = 9 * NCB;

    const __half* gw   = (MODE == 0) ? g_wA1 : g_wA2;
    const __half* gact = (MODE == 0) ? g_h1 : g_h2;

    const int tid = threadIdx.x, lane = tid & 31, wid = tid >> 5;
    const int Nt = blockIdx.x, Mt = blockIdx.y, img = blockIdx.z;
    const int wm = wid & 1, wn = wid >> 1;       // 2M x 4N
    const int lq = lane >> 2, lr = lane & 3;

    const int4* gwA4 = (const int4*)(gw) + (size_t)Mt * NKC * 1024;
    const __half* actimg = gact + (size_t)img * PP * CIN;

    const int jq = tid & 7;
    int bctr[6];
#pragma unroll
    for (int i = 0; i < 6; i++) {
        int p = Nt * NTILE + (tid >> 3) + 32 * i;
        if (p > 360) p = 360;
        bctr[i] = (p / 19 + 1) * 24 + (p % 19) + 1;
    }

    const int amrow = wm * 64 + (lane & 7) + 8 * ((lane >> 3) & 1);
    const int amkof = 8 * (lane >> 4);
    const int bnof = (lane & 7) + 8 * (lane >> 4);
    const int bkof = 8 * ((lane >> 3) & 1);
    const uint32_t smbase = smem_u32(smh);

    float d[4][6][4];
#pragma unroll
    for (int mt = 0; mt < 4; mt++)
#pragma unroll
        for (int nt = 0; nt < 6; nt++)
#pragma unroll
            for (int e = 0; e < 4; e++) d[mt][nt][e] = 0.f;

    auto stage = [&](int kc) {
        const int buf = kc & 1;
        uint32_t Asa = smbase + (buf * BUFH) * 2;
        uint32_t Bsa = Asa + ABUFH * 2;
#pragma unroll
        for (int i = 0; i < 4; i++) {
            int q = tid + i * 256;                // 1024 int4 of A
            int row = q >> 3, ko = (q & 7) << 3;
            cpa16(Asa + (row * ASTH + ko) * 2, gwA4 + (size_t)kc * 1024 + q);
        }
        const int r = kc / NCB, cb = kc - r * NCB;
        const int off = (r / 3) * 24 + (r % 3) - 25;
        const __half* bsrc = actimg + cb * 64 + jq * 8;
#pragma unroll
        for (int i = 0; i < 6; i++) {
            int pix = (tid >> 3) + 32 * i;
            cpa16(Bsa + (pix * BSTH + jq * 8) * 2,
                  bsrc + (size_t)(bctr[i] + off) * CIN);
        }
        CP_COMMIT();
    };

    stage(0);

    for (int kc = 0; kc < NKC; kc++) {
        CP_WAIT0();
        __syncthreads();
        if (kc + 1 < NKC) stage(kc + 1);

        const int buf = kc & 1;
        const uint32_t Asa = smbase + (buf * BUFH) * 2;
        const uint32_t Bsa = Asa + ABUFH * 2;

#pragma unroll
        for (int ks = 0; ks < 4; ks++) {
            uint32_t a[4][4], b[6][2];
#pragma unroll
            for (int mt = 0; mt < 4; mt++)
                ldmx4(a[mt], Asa + ((amrow + mt * 16) * ASTH + ks * 16 + amkof) * 2);
#pragma unroll
            for (int j = 0; j < 3; j++) {
                uint32_t r[4];
                ldmx4(r, Bsa + ((wn * 48 + 16 * j + bnof) * BSTH + ks * 16 + bkof) * 2);
                b[2 * j][0] = r[0]; b[2 * j][1] = r[1];
                b[2 * j + 1][0] = r[2]; b[2 * j + 1][1] = r[3];
            }
#pragma unroll
            for (int mt = 0; mt < 4; mt++)
#pragma unroll
                for (int nt = 0; nt < 6; nt++)
                    mma_f16(d[mt][nt], a[mt], b[nt]);
        }
    }

    // ---- epilogue ----
#pragma unroll
    for (int mt = 0; mt < 4; mt++) {
#pragma unroll
        for (int e2 = 0; e2 < 2; e2++) {
            int row = wm * 64 + mt * 16 + lq + e2 * 8;
            int cout = Mt * 128 + row;
            float sc = 0.f, bs = 0.f;
            if (MODE == 0 && cout >= CR) {
                int c2 = cout - CR;
                sc = bg[c2] * rsqrtf(bv[c2] + EPS);
                bs = fmaf(-bm[c2], sc, bb[c2]);
            }
#pragma unroll
            for (int nt = 0; nt < 6; nt++) {
#pragma unroll
                for (int e1 = 0; e1 < 2; e1++) {
                    int col = wn * 48 + nt * 8 + 2 * lr + e1;
                    int pp = Nt * NTILE + col;
                    if (pp >= HW) continue;
                    float val = d[mt][nt][e2 * 2 + e1];
                    if (MODE == 0) {
                        if (cout < CR)
                            g_reg[((size_t)img * CR + cout) * HW + pp] = val;
                        else
                            g_gp[((size_t)img * CG + (cout - CR)) * HW + pp] =
                                mishf(fmaf(val, sc, bs));
                    } else {
                        size_t off = ((size_t)img * CT + cout) * HW + pp;
                        outp[off] = val + resid[off];
                    }
                }
            }
        }
    }
}

// ---- gpool + linear ----
__global__ void k_gpool(const float* __restrict__ wlin) {
    int img = blockIdx.x;
    int tid = threadIdx.x, warp = tid / 32, lane = tid % 32;
    __shared__ float pooled[3 * CG];
    for (int c = warp; c < CG; c += 8) {
        const float* p = g_gp + ((size_t)img * CG + c) * HW;
        float s = 0.f, mx = -INFINITY;
        for (int i = lane; i < HW; i += 32) {
            float v = p[i];
            s += v; mx = fmaxf(mx, v);
        }
#pragma unroll
        for (int off = 16; off; off >>= 1) {
            s += __shfl_down_sync(0xFFFFFFFFu, s, off);
            mx = fmaxf(mx, __shfl_down_sync(0xFFFFFFFFu, mx, off));
        }
        if (lane == 0) {
            float mean = s * (1.f / 361.f);
            pooled[c] = mean;
            pooled[CG + c] = mean * 0.5f;
            pooled[2 * CG + c] = mx;
        }
    }
    __syncthreads();
    if (tid < CR) {
        float s = 0.f;
        const float* wr = wlin + tid * (3 * CG);
#pragma unroll 4
        for (int k = 0; k < 3 * CG; k++) s = fmaf(pooled[k], wr[k], s);
        g_gpo[img * CR + tid] = s;
    }
}

extern "C" void kernel_launch(void* const* d_in, const int* in_sizes, int n_in,
                              void* d_out, int out_size) {
    const float* x    = (const float*)d_in[0];
    const float* b1g  = (const float*)d_in[1];
    const float* b1b  = (const float*)d_in[2];
    const float* b1m  = (const float*)d_in[3];
    const float* b1v  = (const float*)d_in[4];
    const float* w1a  = (const float*)d_in[5];
    const float* w1b  = (const float*)d_in[6];
    const float* bgg  = (const float*)d_in[7];
    const float* bgb  = (const float*)d_in[8];
    const float* bgm  = (const float*)d_in[9];
    const float* bgv  = (const float*)d_in[10];
    const float* wlin = (const float*)d_in[11];
    const float* b2g  = (const float*)d_in[12];
    const float* b2b  = (const float*)d_in[13];
    const float* b2m  = (const float*)d_in[14];
    const float* b2v  = (const float*)d_in[15];
    const float* w2   = (const float*)d_in[16];
    float* out = (float*)d_out;

    cudaFuncSetAttribute(k_convtc<CT, NCB1, 0>, cudaFuncAttributeMaxDynamicSharedMemorySize, SMEMSZ);
    cudaFuncSetAttribute(k_convtc<CR, NCB2, 1>, cudaFuncAttributeMaxDynamicSharedMemorySize, SMEMSZ);

    k_zero<<<Bn * PP, 64>>>();
    k_wA1<<<(2 * NKC1 * 8192 + 255) / 256, 256>>>(w1a, w1b);
    k_wA2<<<(2 * NKC2 * 8192 + 255) / 256, 256>>>(w2);

    // act1 (bn1+mish, NHWC) -> conv1
    k_act<CT, 0><<<dim3(NCB1, Bn), 256>>>(x, b1g, b1b, b1m, b1v);
    dim3 gconv(2, 2, Bn);
    k_convtc<CT, NCB1, 0><<<gconv, 256, SMEMSZ>>>(bgg, bgb, bgm, bgv, nullptr, nullptr);

    k_gpool<<<Bn, 256>>>(wlin);

    // act2 (reg+gpo, bn2+mish, NHWC; g_reg referenced in device code) -> conv2
    k_act<CR, 1><<<dim3(NCB2, Bn), 256>>>(nullptr, b2g, b2b, b2m, b2v);
    k_convtc<CR, NCB2, 1><<<gconv, 256, SMEMSZ>>>(nullptr, nullptr, nullptr, nullptr, x, out);
}